// round 12
// baseline (speedup 1.0000x reference)
#include <cuda_runtime.h>
#include <math.h>

#define BS   8
#define HW   1024
#define STEP 20
#define NS   51            // hw // STEP
#define NP   512           // model points
#define NBLK (BS * NS)     // 408 hypotheses
#define NT   256           // threads per block (8 warps)
#define NTILE (NP / 8)     // 64 n-tiles of 8 GT points
#define SW   520           // smem row stride (floats), bank-conflict padding
#define SCORING_WEIGHT 0.01f

// Scratch (no allocations allowed)
__device__ float    g_part[NBLK];
__device__ unsigned g_count = 0;   // last-block-done counter; self-resetting

__device__ __forceinline__ unsigned f2tf(float f) {
    unsigned r; asm("cvt.rna.tf32.f32 %0, %1;" : "=r"(r) : "f"(f)); return r;
}

// D = A(tf32 m16k8,row) * B(tf32 k8n8,col) + {Z,Z,Z,Z}
#define MMA_INIT(D0,D1,D2,D3,A0,A1,A2,A3,B0,B1,Z)                              \
    asm("mma.sync.aligned.m16n8k8.row.col.f32.tf32.tf32.f32 "                  \
        "{%0,%1,%2,%3}, {%4,%5,%6,%7}, {%8,%9}, {%10,%10,%10,%10};"            \
        : "=f"(D0),"=f"(D1),"=f"(D2),"=f"(D3)                                  \
        : "r"(A0),"r"(A1),"r"(A2),"r"(A3), "r"(B0),"r"(B1), "f"(Z))

// D += A * B (accumulate in place)
#define MMA_ACC(D0,D1,D2,D3,A0,A1,A2,A3,B0,B1)                                 \
    asm("mma.sync.aligned.m16n8k8.row.col.f32.tf32.tf32.f32 "                  \
        "{%0,%1,%2,%3}, {%4,%5,%6,%7}, {%8,%9}, {%0,%1,%2,%3};"                \
        : "+f"(D0),"+f"(D1),"+f"(D2),"+f"(D3)                                  \
        : "r"(A0),"r"(A1),"r"(A2),"r"(A3), "r"(B0),"r"(B1))

// ---------------------------------------------------------------------------
// One block per (batch, sample) hypothesis, 8 warps. Tensor-core NN:
//   A (m16 x k8) = [-2*pred_hi (k=0..2) | pad=1 | -2*pred_lo | pad=0]
//   B (k8 x n8)  = mma1: [gt_hi|gn_hi repeated]  mma2: [gt_lo|gn_lo, zeros]
// giving D = gn - 2 p.g with split-tf32 (~fp32) accuracy; min folded into
// register accumulators via 4 FMNMX per tile. Warp w owns m-rows [64w,64w+64)
// (4 m-tiles, A fragments register-resident), iterates 64 n-tiles.
// ---------------------------------------------------------------------------
__global__ __launch_bounds__(NT, 3) void fused_kernel(
    const float* __restrict__ pred_r,
    const float* __restrict__ pred_t,
    const float* __restrict__ pred_s,
    const float* __restrict__ gt_r,
    const float* __restrict__ gt_t,
    const float* __restrict__ model,
    float* __restrict__ out)
{
    __shared__ unsigned ps_hi[4 * SW], ps_lo[4 * SW];  // A source: [-2p | 1]
    __shared__ unsigned gs_hi[4 * SW], gs_lo[4 * SW];  // B source: [g | gn]
    __shared__ float    pn_s[NP];
    __shared__ float    red[NT];
    __shared__ bool     s_last;

    int blk = blockIdx.x;
    int b   = blk / NS;
    int pix = (blk % NS) * STEP;
    int tid = threadIdx.x;

    const float* m = model + b * 3 * NP;

    // ---- pose (tiny, redundant per thread) ----
    const float* pr = pred_r + b * 4 * HW + pix;
    float q0 = pr[0], q1 = pr[HW], q2 = pr[2 * HW], q3 = pr[3 * HW];
    float inv = rsqrtf(q0 * q0 + q1 * q1 + q2 * q2 + q3 * q3);
    q0 *= inv; q1 *= inv; q2 *= inv; q3 *= inv;

    float R00 = 1.0f - 2.0f * (q2 * q2 + q3 * q3);
    float R01 = 2.0f * (q1 * q2 - q0 * q3);
    float R02 = 2.0f * (q0 * q2 + q1 * q3);
    float R10 = 2.0f * (q1 * q2 + q3 * q0);
    float R11 = 1.0f - 2.0f * (q1 * q1 + q3 * q3);
    float R12 = 2.0f * (q2 * q3 - q0 * q1);
    float R20 = 2.0f * (q1 * q3 - q0 * q2);
    float R21 = 2.0f * (q0 * q1 + q2 * q3);
    float R22 = 1.0f - 2.0f * (q1 * q1 + q2 * q2);

    const float* pt = pred_t + b * 3 * HW + pix;
    float tx = pt[0], ty = pt[HW], tz = pt[2 * HW];

    const float* GR = gt_r + b * 9;
    const float* GT = gt_t + b * 3;
    float G0 = GR[0], G1 = GR[1], G2 = GR[2];
    float G3 = GR[3], G4 = GR[4], G5 = GR[5];
    float G6 = GR[6], G7 = GR[7], G8 = GR[8];
    float T0 = GT[0], T1 = GT[1], T2 = GT[2];

    // ---- stage A/B sources in smem (2 model points per thread) ----
#pragma unroll
    for (int k = 0; k < 2; k++) {
        int p = tid + k * NT;
        float vx = m[p], vy = m[NP + p], vz = m[2 * NP + p];

        // pred point (query)
        float px = fmaf(R00, vx, fmaf(R01, vy, fmaf(R02, vz, tx)));
        float py = fmaf(R10, vx, fmaf(R11, vy, fmaf(R12, vz, ty)));
        float pz = fmaf(R20, vx, fmaf(R21, vy, fmaf(R22, vz, tz)));
        pn_s[p] = fmaf(px, px, fmaf(py, py, pz * pz));
        float av[3] = { -2.0f * px, -2.0f * py, -2.0f * pz };
#pragma unroll
        for (int c = 0; c < 3; c++) {
            unsigned hi = f2tf(av[c]);
            ps_hi[c * SW + p] = hi;
            ps_lo[c * SW + p] = f2tf(av[c] - __uint_as_float(hi));
        }
        ps_hi[3 * SW + p] = f2tf(1.0f);
        ps_lo[3 * SW + p] = 0u;

        // gt point (candidate)
        float gx = fmaf(G0, vx, fmaf(G1, vy, fmaf(G2, vz, T0)));
        float gy = fmaf(G3, vx, fmaf(G4, vy, fmaf(G5, vz, T1)));
        float gz = fmaf(G6, vx, fmaf(G7, vy, fmaf(G8, vz, T2)));
        float gn = fmaf(gx, gx, fmaf(gy, gy, gz * gz));
        float gv[4] = { gx, gy, gz, gn };
#pragma unroll
        for (int c = 0; c < 4; c++) {
            unsigned hi = f2tf(gv[c]);
            gs_hi[c * SW + p] = hi;
            gs_lo[c * SW + p] = f2tf(gv[c] - __uint_as_float(hi));
        }
    }
    __syncthreads();

    int lane = tid & 31;
    int w    = tid >> 5;       // warp 0..7
    int lq   = lane >> 2;      // 0..7
    int lk   = lane & 3;       // 0..3
    int mbase = w * 64;

    // ---- A fragments for 4 m-tiles (register-resident all loop long) ----
    unsigned Ah0[4], Ah1[4], Al0[4], Al1[4];
#pragma unroll
    for (int mt = 0; mt < 4; mt++) {
        int r0 = mbase + mt * 16 + lq;
        Ah0[mt] = ps_hi[lk * SW + r0];
        Ah1[mt] = ps_hi[lk * SW + r0 + 8];
        Al0[mt] = ps_lo[lk * SW + r0];
        Al1[mt] = ps_lo[lk * SW + r0 + 8];
    }

    float mn[4][4];
#pragma unroll
    for (int mt = 0; mt < 4; mt++)
#pragma unroll
        for (int j = 0; j < 4; j++) mn[mt][j] = 3.0e38f;

    const unsigned* bhp = gs_hi + lk * SW + lq;
    const unsigned* blp = gs_lo + lk * SW + lq;
    unsigned bz = 0u;
    float    fz = 0.0f;

    // ---- main loop: 64 n-tiles x 4 m-tiles; 2 HMMA + 4 FMNMX per tile ----
#pragma unroll 2
    for (int nt = 0; nt < NTILE; nt++) {
        unsigned bh = bhp[nt * 8];
        unsigned bl = blp[nt * 8];
#pragma unroll
        for (int mt = 0; mt < 4; mt++) {
            float d0, d1, d2, d3;
            MMA_INIT(d0, d1, d2, d3,
                     Ah0[mt], Ah1[mt], Al0[mt], Al1[mt], bh, bh, fz);
            MMA_ACC(d0, d1, d2, d3,
                    Ah0[mt], Ah1[mt], Al0[mt], Al1[mt], bl, bz);
            mn[mt][0] = fminf(mn[mt][0], d0);
            mn[mt][1] = fminf(mn[mt][1], d1);
            mn[mt][2] = fminf(mn[mt][2], d2);
            mn[mt][3] = fminf(mn[mt][3], d3);
        }
    }

    // ---- epilogue: quad-min, sqrt, sum ----
    float acc = 0.0f;
#pragma unroll
    for (int mt = 0; mt < 4; mt++) {
        float m0 = fminf(mn[mt][0], mn[mt][1]);   // row mbase+mt*16+lq
        float m1 = fminf(mn[mt][2], mn[mt][3]);   // row +8
#pragma unroll
        for (int off = 1; off <= 2; off <<= 1) {
            m0 = fminf(m0, __shfl_xor_sync(0xFFFFFFFFu, m0, off));
            m1 = fminf(m1, __shfl_xor_sync(0xFFFFFFFFu, m1, off));
        }
        if (lk == 0) {
            int r = mbase + mt * 16 + lq;
            acc += sqrtf(fmaxf(pn_s[r] + m0, 0.0f));
            acc += sqrtf(fmaxf(pn_s[r + 8] + m1, 0.0f));
        }
    }
    red[tid] = acc;          // non-(lk==0) threads contribute 0
    __syncthreads();

#pragma unroll
    for (int s = NT / 2; s >= 32; s >>= 1) {   // fold down to 32 inclusive
        if (tid < s) red[tid] += red[tid + s];
        __syncthreads();
    }
    if (tid < 32) {
        float v = red[tid];
#pragma unroll
        for (int o = 16; o > 0; o >>= 1)
            v += __shfl_down_sync(0xFFFFFFFFu, v, o);
        if (tid == 0) {
            float add = v * (1.0f / NP);
            float sc  = pred_s[b * HW + pix];
            g_part[blk] = (add * sc - SCORING_WEIGHT * logf(sc)) * (1.0f / NBLK);
            __threadfence();
            unsigned old = atomicAdd(&g_count, 1u);
            s_last = (old == NBLK - 1);
        }
    }
    __syncthreads();

    // ---- last CTA: reduce 408 partials + inf/nan guard ----
    if (s_last && tid < 32) {
        __threadfence();
        float v = 0.0f;
        for (int i = tid; i < NBLK; i += 32) v += __ldcg(&g_part[i]);
#pragma unroll
        for (int o = 16; o > 0; o >>= 1)
            v += __shfl_down_sync(0xFFFFFFFFu, v, o);
        if (tid == 0) {
            if (isinf(v) || isnan(v)) v = 0.0f;
            out[0] = v;
            g_count = 0;   // reset for next launch / graph replay
        }
    }
}

// ---------------------------------------------------------------------------
// Inputs (metadata order): pred_r, pred_t, pred_s, mask, gt_r, gt_t,
//                          model_xyz, cls_ids
// ---------------------------------------------------------------------------
extern "C" void kernel_launch(void* const* d_in, const int* in_sizes, int n_in,
                              void* d_out, int out_size)
{
    const float* pred_r = (const float*)d_in[0];
    const float* pred_t = (const float*)d_in[1];
    const float* pred_s = (const float*)d_in[2];
    // d_in[3] = mask (unused)
    const float* gt_r   = (const float*)d_in[4];
    const float* gt_t   = (const float*)d_in[5];
    const float* model  = (const float*)d_in[6];
    // d_in[7] = cls_ids (unused)

    fused_kernel<<<NBLK, NT>>>(pred_r, pred_t, pred_s, gt_r, gt_t, model,
                               (float*)d_out);
}